// round 1
// baseline (speedup 1.0000x reference)
#include <cuda_runtime.h>
#include <math.h>

#define Hd 64
#define Wd 64
#define HW 4096
#define Cc 128
#define Bn 4
#define OUTC 256
#define EPSf 1e-5f

// ---------------- scratch (device globals: allocation-free) ----------------
__device__ float g_dw[2][Bn][Cc][HW];        // Fi_dw, Fw_dw           16 MB
__device__ float g_qkv[6][Bn][Cc][HW];       // Qi,Ki,Vi,Qw,Kw,Vw      48 MB
__device__ float g_S[2][Bn][HW][HW];         // S1, S2                536 MB
__device__ float g_mx[2][Bn][HW];
__device__ float g_rs[2][Bn][HW];
__device__ float g_xcat[Bn][512][HW];        // [A_i; A_w; F_i; F_w]   32 MB
__device__ float g_wcat[OUTC][512];
__device__ float g_bcat[OUTC];

// ---------------- BN (eval) + depthwise 3x3 SAME, fused ----------------
__global__ void __launch_bounds__(256) bn_dw_kernel(
    const float* __restrict__ x, const float* __restrict__ gamma,
    const float* __restrict__ beta, const float* __restrict__ mean,
    const float* __restrict__ var, const float* __restrict__ wdw,
    const float* __restrict__ bdw, float* __restrict__ y)
{
    __shared__ float tile[66 * 66];
    int bc = blockIdx.x;            // b*128 + c
    int c = bc & 127;
    const float* xp = x + (size_t)bc * HW;
    float sc = gamma[c] * rsqrtf(var[c] + EPSf);
    float sh = beta[c] - mean[c] * sc;
    for (int idx = threadIdx.x; idx < 66 * 66; idx += 256) {
        int r = idx / 66 - 1, col = idx % 66 - 1;
        float v = 0.f;
        if (r >= 0 && r < 64 && col >= 0 && col < 64)
            v = xp[r * 64 + col] * sc + sh;   // pad zeros AFTER normalize (matches SAME conv of Fn)
        tile[idx] = v;
    }
    __syncthreads();
    float w0 = wdw[c*9+0], w1 = wdw[c*9+1], w2 = wdw[c*9+2];
    float w3 = wdw[c*9+3], w4 = wdw[c*9+4], w5 = wdw[c*9+5];
    float w6 = wdw[c*9+6], w7 = wdw[c*9+7], w8 = wdw[c*9+8];
    float bb = bdw[c];
    float* yp = y + (size_t)bc * HW;
    for (int idx = threadIdx.x; idx < HW; idx += 256) {
        int r = idx >> 6, col = idx & 63;
        const float* t = &tile[r * 66 + col];
        float s = bb;
        s += t[0]   * w0 + t[1]   * w1 + t[2]   * w2;
        s += t[66]  * w3 + t[67]  * w4 + t[68]  * w5;
        s += t[132] * w6 + t[133] * w7 + t[134] * w8;
        yp[idx] = s;
    }
}

// ---------------- generic 128x128x8 SGEMM, NN (A row-major [M,K]) ----------------
// C[b][m][n] = sum_k A[m][k] * f(B[b][k][n]) + bias[m]
// f = exp(x - mx[k]) * rs[k] when mx != nullptr (softmax-normalize applied to B rows).
__global__ void __launch_bounds__(256) gemm_nn(
    const float* __restrict__ A, const float* __restrict__ B,
    float* __restrict__ Cp, const float* __restrict__ bias,
    const float* __restrict__ mx, const float* __restrict__ rs,
    int N, int K,
    long long bsA, long long bsB, long long bsC)
{
    int b = blockIdx.z;
    A += (long long)b * bsA;
    B += (long long)b * bsB;
    Cp += (long long)b * bsC;
    const float* mxp = mx ? mx + (long long)b * HW : nullptr;
    const float* rsp = rs ? rs + (long long)b * HW : nullptr;
    int m0 = blockIdx.y * 128, n0 = blockIdx.x * 128;

    __shared__ float As[8][128];
    __shared__ float Bs[8][128];
    float acc[8][8];
#pragma unroll
    for (int i = 0; i < 8; i++)
#pragma unroll
        for (int j = 0; j < 8; j++) acc[i][j] = 0.f;

    int tid = threadIdx.x;
    int tx = tid & 15, ty = tid >> 4;
    int ra = tid >> 1, ka = (tid & 1) * 4;     // A: 128 rows x 8 k
    int kb = tid >> 5, cb = (tid & 31) * 4;    // B: 8 k x 128 n

    for (int k0 = 0; k0 < K; k0 += 8) {
        float4 av = *(const float4*)(A + (long long)(m0 + ra) * K + k0 + ka);
        float4 bv = *(const float4*)(B + (long long)(k0 + kb) * N + n0 + cb);
        if (mxp) {
            float mm = mxp[k0 + kb], rr = rsp[k0 + kb];
            bv.x = __expf(bv.x - mm) * rr;
            bv.y = __expf(bv.y - mm) * rr;
            bv.z = __expf(bv.z - mm) * rr;
            bv.w = __expf(bv.w - mm) * rr;
        }
        __syncthreads();
        As[ka + 0][ra] = av.x; As[ka + 1][ra] = av.y;
        As[ka + 2][ra] = av.z; As[ka + 3][ra] = av.w;
        *(float4*)&Bs[kb][cb] = bv;
        __syncthreads();
#pragma unroll
        for (int kk = 0; kk < 8; kk++) {
            float a[8], bb2[8];
            *(float4*)a        = *(const float4*)&As[kk][ty * 8];
            *(float4*)(a + 4)  = *(const float4*)&As[kk][ty * 8 + 4];
            *(float4*)bb2      = *(const float4*)&Bs[kk][tx * 8];
            *(float4*)(bb2+4)  = *(const float4*)&Bs[kk][tx * 8 + 4];
#pragma unroll
            for (int i = 0; i < 8; i++)
#pragma unroll
                for (int j = 0; j < 8; j++)
                    acc[i][j] = fmaf(a[i], bb2[j], acc[i][j]);
        }
    }
#pragma unroll
    for (int i = 0; i < 8; i++) {
        float bi = bias ? bias[m0 + ty * 8 + i] : 0.f;
        float* crow = Cp + (long long)(m0 + ty * 8 + i) * N + n0 + tx * 8;
        float4 o0 = make_float4(acc[i][0] + bi, acc[i][1] + bi, acc[i][2] + bi, acc[i][3] + bi);
        float4 o1 = make_float4(acc[i][4] + bi, acc[i][5] + bi, acc[i][6] + bi, acc[i][7] + bi);
        *(float4*)crow = o0;
        *(float4*)(crow + 4) = o1;
    }
}

// ---------------- 128x128x8 SGEMM, TN: C[b][n][m] = sum_c A[b][c][n] * B[b][c][m] ----------------
__global__ void __launch_bounds__(256) gemm_tn(
    const float* __restrict__ A, const float* __restrict__ B,
    float* __restrict__ Cp, int N, int K, int lda,
    long long bsA, long long bsB, long long bsC)
{
    int b = blockIdx.z;
    A += (long long)b * bsA;
    B += (long long)b * bsB;
    Cp += (long long)b * bsC;
    int m0 = blockIdx.y * 128, n0 = blockIdx.x * 128;

    __shared__ float As[8][128];
    __shared__ float Bs[8][128];
    float acc[8][8];
#pragma unroll
    for (int i = 0; i < 8; i++)
#pragma unroll
        for (int j = 0; j < 8; j++) acc[i][j] = 0.f;

    int tid = threadIdx.x;
    int tx = tid & 15, ty = tid >> 4;
    int kb = tid >> 5, cb = (tid & 31) * 4;

    for (int k0 = 0; k0 < K; k0 += 8) {
        float4 av = *(const float4*)(A + (long long)(k0 + kb) * lda + m0 + cb);
        float4 bv = *(const float4*)(B + (long long)(k0 + kb) * N + n0 + cb);
        __syncthreads();
        *(float4*)&As[kb][cb] = av;
        *(float4*)&Bs[kb][cb] = bv;
        __syncthreads();
#pragma unroll
        for (int kk = 0; kk < 8; kk++) {
            float a[8], bb2[8];
            *(float4*)a        = *(const float4*)&As[kk][ty * 8];
            *(float4*)(a + 4)  = *(const float4*)&As[kk][ty * 8 + 4];
            *(float4*)bb2      = *(const float4*)&Bs[kk][tx * 8];
            *(float4*)(bb2+4)  = *(const float4*)&Bs[kk][tx * 8 + 4];
#pragma unroll
            for (int i = 0; i < 8; i++)
#pragma unroll
                for (int j = 0; j < 8; j++)
                    acc[i][j] = fmaf(a[i], bb2[j], acc[i][j]);
        }
    }
#pragma unroll
    for (int i = 0; i < 8; i++) {
        float* crow = Cp + (long long)(m0 + ty * 8 + i) * N + n0 + tx * 8;
        float4 o0 = make_float4(acc[i][0], acc[i][1], acc[i][2], acc[i][3]);
        float4 o1 = make_float4(acc[i][4], acc[i][5], acc[i][6], acc[i][7]);
        *(float4*)crow = o0;
        *(float4*)(crow + 4) = o1;
    }
}

// ---------------- per-row softmax stats: max + 1/sum(exp) ----------------
__global__ void __launch_bounds__(256) rowstats(
    const float* __restrict__ S, float* __restrict__ mx, float* __restrict__ rs)
{
    long long row = (long long)blockIdx.y * 4096 + blockIdx.x;  // y in [0,8): (attn,b)
    const float4* p = (const float4*)(S + row * 4096);
    __shared__ float red[256];
    float m = -1e30f;
    for (int i = threadIdx.x; i < 1024; i += 256) {
        float4 v = p[i];
        m = fmaxf(fmaxf(m, v.x), fmaxf(v.y, fmaxf(v.z, v.w)));
    }
    red[threadIdx.x] = m; __syncthreads();
    for (int s = 128; s > 0; s >>= 1) {
        if (threadIdx.x < s) red[threadIdx.x] = fmaxf(red[threadIdx.x], red[threadIdx.x + s]);
        __syncthreads();
    }
    m = red[0];
    __syncthreads();
    float sum = 0.f;
    for (int i = threadIdx.x; i < 1024; i += 256) {
        float4 v = p[i];
        sum += __expf(v.x - m) + __expf(v.y - m) + __expf(v.z - m) + __expf(v.w - m);
    }
    red[threadIdx.x] = sum; __syncthreads();
    for (int s = 128; s > 0; s >>= 1) {
        if (threadIdx.x < s) red[threadIdx.x] += red[threadIdx.x + s];
        __syncthreads();
    }
    if (threadIdx.x == 0) { mx[row] = m; rs[row] = 1.f / red[0]; }
}

// ---------------- pack F_i, F_w into xcat rows [256:384) and [384:512) ----------------
__global__ void __launch_bounds__(256) packx(
    const float* __restrict__ Fi, const float* __restrict__ Fw, float* __restrict__ xcat)
{
    int idx = blockIdx.x * 256 + threadIdx.x;
    const int per = Bn * Cc * HW / 4;    // 524288 float4 per tensor
    if (idx >= 2 * per) return;
    int t = idx / per, r = idx % per;
    int b = r / (Cc * HW / 4);
    int rem = r % (Cc * HW / 4);
    int c = rem / (HW / 4);
    int m4 = rem % (HW / 4);
    const float4* src = (const float4*)(t ? Fw : Fi);
    float4* dst = (float4*)xcat;
    dst[(long long)b * (512 * HW / 4) + (long long)(256 + t * Cc + c) * (HW / 4) + m4] = src[r];
}

// ---------------- pack fused output weight [256,512] and bias ----------------
__global__ void __launch_bounds__(256) packw(
    const float* __restrict__ wproj, const float* __restrict__ bproj,
    const float* __restrict__ wres1, const float* __restrict__ bres1,
    const float* __restrict__ wres2, const float* __restrict__ bres2,
    float* __restrict__ wcat, float* __restrict__ bcat)
{
    int idx = blockIdx.x * 256 + threadIdx.x;   // 256*512 total
    if (idx >= OUTC * 512) return;
    int o = idx >> 9, k = idx & 511;
    float v;
    if (k < 256)      v = wproj[o * 256 + k];
    else if (k < 384) v = wres1[o * 128 + k - 256];
    else              v = wres2[o * 128 + k - 384];
    wcat[idx] = v;
    if (k == 0) bcat[o] = bproj[o] + bres1[o] + bres2[o];
}

// ---------------- launch ----------------
extern "C" void kernel_launch(void* const* d_in, const int* in_sizes, int n_in,
                              void* d_out, int out_size)
{
    const float* F_i   = (const float*)d_in[0];
    const float* F_w   = (const float*)d_in[1];
    const float* bn1_g = (const float*)d_in[2];
    const float* bn1_b = (const float*)d_in[3];
    const float* bn1_m = (const float*)d_in[4];
    const float* bn1_v = (const float*)d_in[5];
    const float* bn2_g = (const float*)d_in[6];
    const float* bn2_b = (const float*)d_in[7];
    const float* bn2_m = (const float*)d_in[8];
    const float* bn2_v = (const float*)d_in[9];
    const float* wq1 = (const float*)d_in[10];  const float* bq1 = (const float*)d_in[11];
    const float* wk1 = (const float*)d_in[12];  const float* bk1 = (const float*)d_in[13];
    const float* wv1 = (const float*)d_in[14];  const float* bv1 = (const float*)d_in[15];
    const float* wq2 = (const float*)d_in[16];  const float* bq2 = (const float*)d_in[17];
    const float* wk2 = (const float*)d_in[18];  const float* bk2 = (const float*)d_in[19];
    const float* wv2 = (const float*)d_in[20];  const float* bv2 = (const float*)d_in[21];
    const float* wdw1 = (const float*)d_in[22]; const float* bdw1 = (const float*)d_in[23];
    const float* wdw2 = (const float*)d_in[24]; const float* bdw2 = (const float*)d_in[25];
    const float* wproj = (const float*)d_in[26]; const float* bproj = (const float*)d_in[27];
    const float* wres1 = (const float*)d_in[28]; const float* bres1 = (const float*)d_in[29];
    const float* wres2 = (const float*)d_in[30]; const float* bres2 = (const float*)d_in[31];

    float *dw, *qkv, *S, *mx, *rs, *xcat, *wcat, *bcat;
    cudaGetSymbolAddress((void**)&dw,   g_dw);
    cudaGetSymbolAddress((void**)&qkv,  g_qkv);
    cudaGetSymbolAddress((void**)&S,    g_S);
    cudaGetSymbolAddress((void**)&mx,   g_mx);
    cudaGetSymbolAddress((void**)&rs,   g_rs);
    cudaGetSymbolAddress((void**)&xcat, g_xcat);
    cudaGetSymbolAddress((void**)&wcat, g_wcat);
    cudaGetSymbolAddress((void**)&bcat, g_bcat);

    const long long szT = (long long)Bn * Cc * HW;      // 2,097,152 floats (one [B,C,HW] tensor)
    const long long szS = (long long)Bn * HW * HW;      // one attention's S, all batches

    // 1. pack fused output weights
    packw<<<512, 256>>>(wproj, bproj, wres1, bres1, wres2, bres2, wcat, bcat);

    // 2. BN + depthwise
    bn_dw_kernel<<<Bn * Cc, 256>>>(F_i, bn1_g, bn1_b, bn1_m, bn1_v, wdw1, bdw1, dw);
    bn_dw_kernel<<<Bn * Cc, 256>>>(F_w, bn2_g, bn2_b, bn2_m, bn2_v, wdw2, bdw2, dw + szT);

    // 3. pack raw F_i/F_w into xcat residual slots
    packx<<<4096, 256>>>(F_i, F_w, xcat);

    // 4. QKV 1x1 convs (GEMM M=128,N=4096,K=128). buffers: 0=Qi 1=Ki 2=Vi 3=Qw 4=Kw 5=Vw
    dim3 gq(32, 1, Bn);
    long long bsT = (long long)Cc * HW;
    gemm_nn<<<gq, 256>>>(wq1, dw,        qkv + 0 * szT, bq1, nullptr, nullptr, HW, Cc, 0, bsT, bsT);
    gemm_nn<<<gq, 256>>>(wk1, dw,        qkv + 1 * szT, bk1, nullptr, nullptr, HW, Cc, 0, bsT, bsT);
    gemm_nn<<<gq, 256>>>(wv1, dw,        qkv + 2 * szT, bv1, nullptr, nullptr, HW, Cc, 0, bsT, bsT);
    gemm_nn<<<gq, 256>>>(wq2, dw + szT,  qkv + 3 * szT, bq2, nullptr, nullptr, HW, Cc, 0, bsT, bsT);
    gemm_nn<<<gq, 256>>>(wk2, dw + szT,  qkv + 4 * szT, bk2, nullptr, nullptr, HW, Cc, 0, bsT, bsT);
    gemm_nn<<<gq, 256>>>(wv2, dw + szT,  qkv + 5 * szT, bv2, nullptr, nullptr, HW, Cc, 0, bsT, bsT);

    // 5. S1 = Qi^T Kw ; S2 = Qw^T Ki   (TN GEMM, M=N=4096, K=128)
    dim3 gs(32, 32, Bn);
    gemm_tn<<<gs, 256>>>(qkv + 0 * szT, qkv + 4 * szT, S,       HW, Cc, HW, bsT, bsT, (long long)HW * HW);
    gemm_tn<<<gs, 256>>>(qkv + 3 * szT, qkv + 1 * szT, S + szS, HW, Cc, HW, bsT, bsT, (long long)HW * HW);

    // 6. softmax row stats for both attentions
    dim3 gst(4096, 8);
    rowstats<<<gst, 256>>>(S, mx, rs);

    // 7. A_i = Vw @ softmax(S1) -> xcat[:,0:128] ; A_w = Vi @ softmax(S2) -> xcat[:,128:256]
    dim3 gav(32, 1, Bn);
    gemm_nn<<<gav, 256>>>(qkv + 5 * szT, S,       xcat,            nullptr, mx,            rs,
                          HW, HW, bsT, (long long)HW * HW, 512LL * HW);
    gemm_nn<<<gav, 256>>>(qkv + 2 * szT, S + szS, xcat + 128 * HW, nullptr, mx + Bn * HW, rs + Bn * HW,
                          HW, HW, bsT, (long long)HW * HW, 512LL * HW);

    // 8. out = Wcat @ xcat + bcat   (M=256, N=4096, K=512)
    dim3 gf(32, 2, Bn);
    gemm_nn<<<gf, 256>>>(wcat, xcat, (float*)d_out, bcat, nullptr, nullptr,
                         HW, 512, 0, 512LL * HW, (long long)OUTC * HW);
}